// round 13
// baseline (speedup 1.0000x reference)
#include <cuda_runtime.h>
#include <cuda_bf16.h>
#include <mma.h>
#include <cstdint>

using namespace nvcuda;

#define N_ 65536
#define D_ 1024
#define K_ 256

#define BM 128
#define BK 32
#define LDS_B 40   /* bf16 per smem row: 32 + 8 pad */

static __device__ __align__(16) __nv_bfloat16 g_cb[K_ * D_];
static __device__ __align__(16) float g_csq[K_];
static __device__ __align__(16) float g_qsum[K_];
static __device__ __align__(16) float g_num[K_ * D_];
static __device__ __align__(16) float g_den[K_];

// ---------------------------------------------------------------------------
// Kernel 1: clusters fp32 -> bf16, ||c||^2, zero accumulators.
// ---------------------------------------------------------------------------
__global__ void prep_kernel(const float* __restrict__ clusters) {
    int gtid = blockIdx.x * blockDim.x + threadIdx.x;
    int w    = gtid >> 5;
    int lane = threadIdx.x & 31;

    if (w < K_) {
        const float* src = clusters + (size_t)w * D_;
        __nv_bfloat16* dst = g_cb + (size_t)w * D_;
        float s = 0.f;
        #pragma unroll
        for (int c = lane; c < D_; c += 32) {
            float v = src[c];
            s += v * v;
            dst[c] = __float2bfloat16(v);
        }
        #pragma unroll
        for (int o = 16; o; o >>= 1) s += __shfl_xor_sync(0xffffffffu, s, o);
        if (lane == 0) g_csq[w] = s;
    }

    if (gtid < K_) { g_qsum[gtid] = 0.f; g_den[gtid] = 0.f; }
    for (int i = gtid; i < K_ * D_; i += 8192) g_num[i] = 0.f;
}

// ---------------------------------------------------------------------------
// Kernel 2: wmma bf16 GEMM (R9 mainloop, untouched) + fused epilogue via an
// L2 roundtrip: store raw dots to q_out, sync, read back, transform
// (t = 1/(1+d), row-normalize), overwrite final q, column sums -> g_qsum.
// 128x256 (full K), BK=32, single-buffered STATIC smem, 256 threads = 8 warps
// (2m x 4n), warp tile 64x64. Fuses ||x||^2.
// ---------------------------------------------------------------------------
__global__ __launch_bounds__(256, 1)
void gemm_kernel(const float* __restrict__ x, float* __restrict__ q_out) {
    __shared__ __align__(16) __nv_bfloat16 As[BM * LDS_B];  /* 10240 B */
    __shared__ __align__(16) __nv_bfloat16 Bs[K_ * LDS_B];  /* 20480 B */
    __shared__ float xsq_s[BM];
    __shared__ float csq_s[K_];
    __shared__ float colsum[K_];

    const int tid  = threadIdx.x;
    const int lane = tid & 31;
    const int wid  = tid >> 5;       // 0..7
    const int wm   = wid & 1;        // 64-row group
    const int wn   = wid >> 1;       // 64-col group
    const int row0 = blockIdx.x * BM;

    if (tid < 128) xsq_s[tid] = 0.f;
    if (tid < 256) { csq_s[tid] = g_csq[tid]; colsum[tid] = 0.f; }

    // loaders: A 2 thr/row x 16 floats; B 4 thr/row x 8 bf16, 4 rows/thread
    const int aRow = tid >> 1;            // 0..127
    const int aCol = (tid & 1) * 16;      // 0,16 (floats)
    const int bRow = tid >> 2;            // 0..63 (+64*i)
    const int bCol = (tid & 3) * 8;       // 0..24 (bf16)

    const float* aP = x + (size_t)(row0 + aRow) * D_ + aCol;
    const __nv_bfloat16* bP = g_cb + (size_t)bRow * D_ + bCol;

    wmma::fragment<wmma::accumulator, 16, 16, 16, float> acc[4][4];
    #pragma unroll
    for (int mi = 0; mi < 4; mi++)
        #pragma unroll
        for (int nj = 0; nj < 4; nj++)
            wmma::fill_fragment(acc[mi][nj], 0.f);

    float4 a0 = *(const float4*)aP;
    float4 a1 = *(const float4*)(aP + 4);
    float4 a2 = *(const float4*)(aP + 8);
    float4 a3 = *(const float4*)(aP + 12);
    uint4  bv[4];
    #pragma unroll
    for (int i = 0; i < 4; i++)
        bv[i] = *(const uint4*)(bP + (size_t)i * 64 * D_);

    float sq = 0.f;

    for (int kt = 0; kt < D_ / BK; ++kt) {
        // commit staged tile (+ ||x||^2 partial)
        {
            __nv_bfloat162* da = (__nv_bfloat162*)&As[aRow * LDS_B + aCol];
            __nv_bfloat162 p;
            p.x = __float2bfloat16(a0.x); p.y = __float2bfloat16(a0.y); da[0] = p;
            p.x = __float2bfloat16(a0.z); p.y = __float2bfloat16(a0.w); da[1] = p;
            p.x = __float2bfloat16(a1.x); p.y = __float2bfloat16(a1.y); da[2] = p;
            p.x = __float2bfloat16(a1.z); p.y = __float2bfloat16(a1.w); da[3] = p;
            p.x = __float2bfloat16(a2.x); p.y = __float2bfloat16(a2.y); da[4] = p;
            p.x = __float2bfloat16(a2.z); p.y = __float2bfloat16(a2.w); da[5] = p;
            p.x = __float2bfloat16(a3.x); p.y = __float2bfloat16(a3.y); da[6] = p;
            p.x = __float2bfloat16(a3.z); p.y = __float2bfloat16(a3.w); da[7] = p;
            sq += a0.x*a0.x + a0.y*a0.y + a0.z*a0.z + a0.w*a0.w
                + a1.x*a1.x + a1.y*a1.y + a1.z*a1.z + a1.w*a1.w
                + a2.x*a2.x + a2.y*a2.y + a2.z*a2.z + a2.w*a2.w
                + a3.x*a3.x + a3.y*a3.y + a3.z*a3.z + a3.w*a3.w;
            #pragma unroll
            for (int i = 0; i < 4; i++)
                *(uint4*)&Bs[(bRow + i * 64) * LDS_B + bCol] = bv[i];
        }
        __syncthreads();

        // prefetch next tile
        if (kt < D_ / BK - 1) {
            const float* ap = aP + (kt + 1) * BK;
            const __nv_bfloat16* bp = bP + (kt + 1) * BK;
            a0 = *(const float4*)ap;
            a1 = *(const float4*)(ap + 4);
            a2 = *(const float4*)(ap + 8);
            a3 = *(const float4*)(ap + 12);
            #pragma unroll
            for (int i = 0; i < 4; i++)
                bv[i] = *(const uint4*)(bp + (size_t)i * 64 * D_);
        }

        // mma: 2 k16 steps, 64x64 warp tile (4x4 fragments)
        #pragma unroll
        for (int ks = 0; ks < 2; ++ks) {
            wmma::fragment<wmma::matrix_b, 16, 16, 16, __nv_bfloat16,
                           wmma::col_major> bfr[4];
            #pragma unroll
            for (int nj = 0; nj < 4; nj++)
                wmma::load_matrix_sync(
                    bfr[nj], &Bs[(wn * 64 + nj * 16) * LDS_B + ks * 16], LDS_B);
            #pragma unroll
            for (int mi = 0; mi < 4; mi++) {
                wmma::fragment<wmma::matrix_a, 16, 16, 16, __nv_bfloat16,
                               wmma::row_major> afr;
                wmma::load_matrix_sync(
                    afr, &As[(wm * 64 + mi * 16) * LDS_B + ks * 16], LDS_B);
                #pragma unroll
                for (int nj = 0; nj < 4; nj++)
                    wmma::mma_sync(acc[mi][nj], afr, bfr[nj], acc[mi][nj]);
            }
        }
        __syncthreads();
    }

    // ||x||^2 publish (2 partials per row)
    atomicAdd(&xsq_s[aRow], sq);

    // dump raw dot products to q_out (stays hot in L2)
    #pragma unroll
    for (int mi = 0; mi < 4; mi++)
        #pragma unroll
        for (int nj = 0; nj < 4; nj++)
            wmma::store_matrix_sync(
                q_out + (size_t)(row0 + wm * 64 + mi * 16) * K_
                      + wn * 64 + nj * 16,
                acc[mi][nj], K_, wmma::mem_row_major);
    __syncthreads();   // orders global stores + xsq within the CTA

    // fused epilogue (reads back via L2): each warp handles 16 rows
    {
        const float4 c0 = *(const float4*)&csq_s[lane * 4];
        const float4 c1 = *(const float4*)&csq_s[128 + lane * 4];
        float cacc[8] = {0.f, 0.f, 0.f, 0.f, 0.f, 0.f, 0.f, 0.f};

        #pragma unroll
        for (int i = 0; i < 16; i++) {
            const int row = wid * 16 + i;
            float* go = q_out + (size_t)(row0 + row) * K_;
            float xs1 = 1.f + xsq_s[row];
            float4 u = *(float4*)(go + lane * 4);
            float4 v = *(float4*)(go + 128 + lane * 4);
            u.x = 1.f / (xs1 + c0.x - 2.f * u.x);
            u.y = 1.f / (xs1 + c0.y - 2.f * u.y);
            u.z = 1.f / (xs1 + c0.z - 2.f * u.z);
            u.w = 1.f / (xs1 + c0.w - 2.f * u.w);
            v.x = 1.f / (xs1 + c1.x - 2.f * v.x);
            v.y = 1.f / (xs1 + c1.y - 2.f * v.y);
            v.z = 1.f / (xs1 + c1.z - 2.f * v.z);
            v.w = 1.f / (xs1 + c1.w - 2.f * v.w);
            float s = u.x + u.y + u.z + u.w + v.x + v.y + v.z + v.w;
            #pragma unroll
            for (int o = 16; o; o >>= 1) s += __shfl_xor_sync(0xffffffffu, s, o);
            float inv = 1.f / s;
            u.x *= inv; u.y *= inv; u.z *= inv; u.w *= inv;
            v.x *= inv; v.y *= inv; v.z *= inv; v.w *= inv;
            *(float4*)(go + lane * 4) = u;
            *(float4*)(go + 128 + lane * 4) = v;
            cacc[0] += u.x; cacc[1] += u.y; cacc[2] += u.z; cacc[3] += u.w;
            cacc[4] += v.x; cacc[5] += v.y; cacc[6] += v.z; cacc[7] += v.w;
        }

        #pragma unroll
        for (int j = 0; j < 4; j++) {
            atomicAdd(&colsum[lane * 4 + j],       cacc[j]);
            atomicAdd(&colsum[128 + lane * 4 + j], cacc[4 + j]);
        }
    }
    __syncthreads();
    if (tid < 256) atomicAdd(&g_qsum[tid], colsum[tid]);
}

// ---------------------------------------------------------------------------
// Kernel 3: sharpening + hard-assign + threshold + scatter. Warp per row.
// ---------------------------------------------------------------------------
__global__ void pass2_kernel(const float* __restrict__ q, const float* __restrict__ x) {
    int row  = blockIdx.x * (blockDim.x >> 5) + (threadIdx.x >> 5);
    int lane = threadIdx.x & 31;
    if (row >= N_) return;

    const float* qr = q + (size_t)row * K_;
    float s2 = 0.f;
    float m = -1.f;
    int   mi = 0;

    #pragma unroll
    for (int j = 0; j < 2; j++) {
        int c = (j * 32 + lane) * 4;
        float4 qv = *(const float4*)(qr + c);
        float4 qs = *(const float4*)(g_qsum + c);
        float t0 = qv.x * qv.x / qs.x;
        float t1 = qv.y * qv.y / qs.y;
        float t2 = qv.z * qv.z / qs.z;
        float t3 = qv.w * qv.w / qs.w;
        s2 += t0 + t1 + t2 + t3;
        if (t0 > m) { m = t0; mi = c; }
        if (t1 > m) { m = t1; mi = c + 1; }
        if (t2 > m) { m = t2; mi = c + 2; }
        if (t3 > m) { m = t3; mi = c + 3; }
    }
    #pragma unroll
    for (int o = 16; o; o >>= 1) {
        s2 += __shfl_xor_sync(0xffffffffu, s2, o);
        float om = __shfl_xor_sync(0xffffffffu, m, o);
        int   oi = __shfl_xor_sync(0xffffffffu, mi, o);
        if (om > m || (om == m && oi < mi)) { m = om; mi = oi; }
    }

    float val = m / s2;
    if (val > 0.1f) {
        if (lane == 0) atomicAdd(&g_den[mi], val);
        const float* xr = x + (size_t)row * D_;
        for (int c = lane; c < D_; c += 32)
            atomicAdd(&g_num[(size_t)mi * D_ + c], val * xr[c]);
    }
}

// ---------------------------------------------------------------------------
// Kernel 4: new_clusters = num / (den + eps)
// ---------------------------------------------------------------------------
__global__ void finalize_kernel(float* __restrict__ out_clusters) {
    int i = blockIdx.x * blockDim.x + threadIdx.x;
    if (i < K_ * D_) {
        int k = i / D_;
        out_clusters[i] = g_num[i] / (g_den[k] + 2.220446049250313e-16f);
    }
}

// ---------------------------------------------------------------------------
extern "C" void kernel_launch(void* const* d_in, const int* in_sizes, int n_in,
                              void* d_out, int out_size) {
    const float* x = nullptr;
    const float* clusters = nullptr;
    for (int i = 0; i < n_in; i++) {
        if (in_sizes[i] == N_ * D_)      x        = (const float*)d_in[i];
        else if (in_sizes[i] == K_ * D_) clusters = (const float*)d_in[i];
    }
    if (!x)        x        = (const float*)d_in[0];
    if (!clusters) clusters = (const float*)d_in[1];

    float* q_out = (float*)d_out;
    float* c_out = (float*)d_out + (size_t)N_ * K_;

    prep_kernel<<<32, 256>>>(clusters);
    gemm_kernel<<<N_ / BM, 256>>>(x, q_out);
    pass2_kernel<<<N_ / 8, 256>>>(q_out, x);
    if (out_size >= (int)((size_t)N_ * K_ + (size_t)K_ * D_)) {
        finalize_kernel<<<(K_ * D_) / 256, 256>>>(c_out);
    }
}

// round 14
// speedup vs baseline: 1.0609x; 1.0609x over previous
#include <cuda_runtime.h>
#include <cuda_bf16.h>
#include <mma.h>
#include <cstdint>

using namespace nvcuda;

#define N_ 65536
#define D_ 1024
#define K_ 256

#define BM 64
#define BK 32
#define LDS_B 40   /* bf16 per smem row: 32 + 8 pad */

static __device__ __align__(16) __nv_bfloat16 g_cb[K_ * D_];
static __device__ __align__(16) float g_csq[K_];
static __device__ __align__(16) float g_xsq[N_];
static __device__ __align__(16) float g_qsum[K_];
static __device__ __align__(16) float g_num[K_ * D_];
static __device__ __align__(16) float g_den[K_];

// ---------------------------------------------------------------------------
// Kernel 1: clusters fp32 -> bf16, ||c||^2, zero accumulators.
// ---------------------------------------------------------------------------
__global__ void prep_kernel(const float* __restrict__ clusters) {
    int gtid = blockIdx.x * blockDim.x + threadIdx.x;
    int w    = gtid >> 5;
    int lane = threadIdx.x & 31;

    if (w < K_) {
        const float* src = clusters + (size_t)w * D_;
        __nv_bfloat16* dst = g_cb + (size_t)w * D_;
        float s = 0.f;
        #pragma unroll
        for (int c = lane; c < D_; c += 32) {
            float v = src[c];
            s += v * v;
            dst[c] = __float2bfloat16(v);
        }
        #pragma unroll
        for (int o = 16; o; o >>= 1) s += __shfl_xor_sync(0xffffffffu, s, o);
        if (lane == 0) g_csq[w] = s;
    }

    if (gtid < K_) { g_qsum[gtid] = 0.f; g_den[gtid] = 0.f; }
    for (int i = gtid; i < K_ * D_; i += 8192) g_num[i] = 0.f;
}

// ---------------------------------------------------------------------------
// Kernel 2: wmma bf16 GEMM, 64x256 (full K) tile, BK=32, single-buffered
// static smem, 256 threads = 8 warps (2m x 4n), warp tile 32x64.
// __launch_bounds__(256,2) -> 2 CTAs/SM for cross-CTA latency hiding.
// Fuses ||x||^2. Writes RAW dot products; transform lives in row_kernel.
// ---------------------------------------------------------------------------
__global__ __launch_bounds__(256, 2)
void gemm_kernel(const float* __restrict__ x, float* __restrict__ q_out) {
    __shared__ __align__(16) __nv_bfloat16 As[BM * LDS_B];  /*  5120 B */
    __shared__ __align__(16) __nv_bfloat16 Bs[K_ * LDS_B];  /* 20480 B */
    __shared__ float xsq_s[BM];

    const int tid  = threadIdx.x;
    const int wid  = tid >> 5;       // 0..7
    const int wm   = wid & 1;        // 32-row group
    const int wn   = wid >> 1;       // 64-col group
    const int row0 = blockIdx.x * BM;

    if (tid < 64) xsq_s[tid] = 0.f;

    // loaders: A 4 thr/row x 8 floats; B 4 thr/row x 8 bf16, 4 rows/thread
    const int aRow = tid >> 2;            // 0..63
    const int aCol = (tid & 3) * 8;       // 0..24 (floats)
    const int bRow = tid >> 2;            // 0..63 (+64*i)
    const int bCol = (tid & 3) * 8;       // 0..24 (bf16)

    const float* aP = x + (size_t)(row0 + aRow) * D_ + aCol;
    const __nv_bfloat16* bP = g_cb + (size_t)bRow * D_ + bCol;

    wmma::fragment<wmma::accumulator, 16, 16, 16, float> acc[2][4];
    #pragma unroll
    for (int mi = 0; mi < 2; mi++)
        #pragma unroll
        for (int nj = 0; nj < 4; nj++)
            wmma::fill_fragment(acc[mi][nj], 0.f);

    float4 a0 = *(const float4*)aP;
    float4 a1 = *(const float4*)(aP + 4);
    uint4  bv[4];
    #pragma unroll
    for (int i = 0; i < 4; i++)
        bv[i] = *(const uint4*)(bP + (size_t)i * 64 * D_);

    float sq = 0.f;

    for (int kt = 0; kt < D_ / BK; ++kt) {
        // commit staged tile (+ ||x||^2 partial)
        {
            __nv_bfloat162* da = (__nv_bfloat162*)&As[aRow * LDS_B + aCol];
            __nv_bfloat162 p;
            p.x = __float2bfloat16(a0.x); p.y = __float2bfloat16(a0.y); da[0] = p;
            p.x = __float2bfloat16(a0.z); p.y = __float2bfloat16(a0.w); da[1] = p;
            p.x = __float2bfloat16(a1.x); p.y = __float2bfloat16(a1.y); da[2] = p;
            p.x = __float2bfloat16(a1.z); p.y = __float2bfloat16(a1.w); da[3] = p;
            sq += a0.x*a0.x + a0.y*a0.y + a0.z*a0.z + a0.w*a0.w
                + a1.x*a1.x + a1.y*a1.y + a1.z*a1.z + a1.w*a1.w;
            #pragma unroll
            for (int i = 0; i < 4; i++)
                *(uint4*)&Bs[(bRow + i * 64) * LDS_B + bCol] = bv[i];
        }
        __syncthreads();

        // prefetch next tile
        if (kt < D_ / BK - 1) {
            const float* ap = aP + (kt + 1) * BK;
            const __nv_bfloat16* bp = bP + (kt + 1) * BK;
            a0 = *(const float4*)ap;
            a1 = *(const float4*)(ap + 4);
            #pragma unroll
            for (int i = 0; i < 4; i++)
                bv[i] = *(const uint4*)(bp + (size_t)i * 64 * D_);
        }

        // mma: 2 k16 steps, 32x64 warp tile (2x4 fragments)
        #pragma unroll
        for (int ks = 0; ks < 2; ++ks) {
            wmma::fragment<wmma::matrix_b, 16, 16, 16, __nv_bfloat16,
                           wmma::col_major> bfr[4];
            #pragma unroll
            for (int nj = 0; nj < 4; nj++)
                wmma::load_matrix_sync(
                    bfr[nj], &Bs[(wn * 64 + nj * 16) * LDS_B + ks * 16], LDS_B);
            #pragma unroll
            for (int mi = 0; mi < 2; mi++) {
                wmma::fragment<wmma::matrix_a, 16, 16, 16, __nv_bfloat16,
                               wmma::row_major> afr;
                wmma::load_matrix_sync(
                    afr, &As[(wm * 32 + mi * 16) * LDS_B + ks * 16], LDS_B);
                #pragma unroll
                for (int nj = 0; nj < 4; nj++)
                    wmma::mma_sync(acc[mi][nj], afr, bfr[nj], acc[mi][nj]);
            }
        }
        __syncthreads();
    }

    // ||x||^2 publish (4 partials per row)
    atomicAdd(&xsq_s[aRow], sq);
    __syncthreads();
    if (tid < 64) g_xsq[row0 + tid] = xsq_s[tid];

    // store raw dot products
    #pragma unroll
    for (int mi = 0; mi < 2; mi++)
        #pragma unroll
        for (int nj = 0; nj < 4; nj++)
            wmma::store_matrix_sync(
                q_out + (size_t)(row0 + wm * 32 + mi * 16) * K_
                      + wn * 64 + nj * 16,
                acc[mi][nj], K_, wmma::mem_row_major);
}

// ---------------------------------------------------------------------------
// Kernel 3: s -> t = 1/(1+d) -> row normalize in place + column sums.
// ---------------------------------------------------------------------------
__global__ __launch_bounds__(512, 2)
void row_kernel(float* __restrict__ q) {
    __shared__ float colsum[K_];
    __shared__ float csq_s[K_];
    const int tid  = threadIdx.x;
    const int lane = tid & 31;
    const int w    = tid >> 5;

    if (tid < 256) { colsum[tid] = 0.f; csq_s[tid] = g_csq[tid]; }
    __syncthreads();

    const int rbase = blockIdx.x * 64 + w * 4;
    float cacc[8] = {0.f, 0.f, 0.f, 0.f, 0.f, 0.f, 0.f, 0.f};

    const float4 c0 = *(const float4*)&csq_s[lane * 4];
    const float4 c1 = *(const float4*)&csq_s[128 + lane * 4];

    #pragma unroll
    for (int i = 0; i < 4; i++) {
        float* qr = q + (size_t)(rbase + i) * K_;
        float xs1 = 1.f + g_xsq[rbase + i];
        float4 u = *(float4*)(qr + lane * 4);
        float4 v = *(float4*)(qr + 128 + lane * 4);
        u.x = 1.f / (xs1 + c0.x - 2.f * u.x);
        u.y = 1.f / (xs1 + c0.y - 2.f * u.y);
        u.z = 1.f / (xs1 + c0.z - 2.f * u.z);
        u.w = 1.f / (xs1 + c0.w - 2.f * u.w);
        v.x = 1.f / (xs1 + c1.x - 2.f * v.x);
        v.y = 1.f / (xs1 + c1.y - 2.f * v.y);
        v.z = 1.f / (xs1 + c1.z - 2.f * v.z);
        v.w = 1.f / (xs1 + c1.w - 2.f * v.w);
        float s = u.x + u.y + u.z + u.w + v.x + v.y + v.z + v.w;
        #pragma unroll
        for (int o = 16; o; o >>= 1) s += __shfl_xor_sync(0xffffffffu, s, o);
        float inv = 1.f / s;
        u.x *= inv; u.y *= inv; u.z *= inv; u.w *= inv;
        v.x *= inv; v.y *= inv; v.z *= inv; v.w *= inv;
        *(float4*)(qr + lane * 4) = u;
        *(float4*)(qr + 128 + lane * 4) = v;
        cacc[0] += u.x; cacc[1] += u.y; cacc[2] += u.z; cacc[3] += u.w;
        cacc[4] += v.x; cacc[5] += v.y; cacc[6] += v.z; cacc[7] += v.w;
    }

    #pragma unroll
    for (int j = 0; j < 4; j++) {
        atomicAdd(&colsum[lane * 4 + j],       cacc[j]);
        atomicAdd(&colsum[128 + lane * 4 + j], cacc[4 + j]);
    }
    __syncthreads();
    if (tid < 256) atomicAdd(&g_qsum[tid], colsum[tid]);
}

// ---------------------------------------------------------------------------
// Kernel 4: sharpening + hard-assign + threshold + scatter. Warp per row.
// ---------------------------------------------------------------------------
__global__ void pass2_kernel(const float* __restrict__ q, const float* __restrict__ x) {
    int row  = blockIdx.x * (blockDim.x >> 5) + (threadIdx.x >> 5);
    int lane = threadIdx.x & 31;
    if (row >= N_) return;

    const float* qr = q + (size_t)row * K_;
    float s2 = 0.f;
    float m = -1.f;
    int   mi = 0;

    #pragma unroll
    for (int j = 0; j < 2; j++) {
        int c = (j * 32 + lane) * 4;
        float4 qv = *(const float4*)(qr + c);
        float4 qs = *(const float4*)(g_qsum + c);
        float t0 = qv.x * qv.x / qs.x;
        float t1 = qv.y * qv.y / qs.y;
        float t2 = qv.z * qv.z / qs.z;
        float t3 = qv.w * qv.w / qs.w;
        s2 += t0 + t1 + t2 + t3;
        if (t0 > m) { m = t0; mi = c; }
        if (t1 > m) { m = t1; mi = c + 1; }
        if (t2 > m) { m = t2; mi = c + 2; }
        if (t3 > m) { m = t3; mi = c + 3; }
    }
    #pragma unroll
    for (int o = 16; o; o >>= 1) {
        s2 += __shfl_xor_sync(0xffffffffu, s2, o);
        float om = __shfl_xor_sync(0xffffffffu, m, o);
        int   oi = __shfl_xor_sync(0xffffffffu, mi, o);
        if (om > m || (om == m && oi < mi)) { m = om; mi = oi; }
    }

    float val = m / s2;
    if (val > 0.1f) {
        if (lane == 0) atomicAdd(&g_den[mi], val);
        const float* xr = x + (size_t)row * D_;
        for (int c = lane; c < D_; c += 32)
            atomicAdd(&g_num[(size_t)mi * D_ + c], val * xr[c]);
    }
}

// ---------------------------------------------------------------------------
// Kernel 5: new_clusters = num / (den + eps)
// ---------------------------------------------------------------------------
__global__ void finalize_kernel(float* __restrict__ out_clusters) {
    int i = blockIdx.x * blockDim.x + threadIdx.x;
    if (i < K_ * D_) {
        int k = i / D_;
        out_clusters[i] = g_num[i] / (g_den[k] + 2.220446049250313e-16f);
    }
}

// ---------------------------------------------------------------------------
extern "C" void kernel_launch(void* const* d_in, const int* in_sizes, int n_in,
                              void* d_out, int out_size) {
    const float* x = nullptr;
    const float* clusters = nullptr;
    for (int i = 0; i < n_in; i++) {
        if (in_sizes[i] == N_ * D_)      x        = (const float*)d_in[i];
        else if (in_sizes[i] == K_ * D_) clusters = (const float*)d_in[i];
    }
    if (!x)        x        = (const float*)d_in[0];
    if (!clusters) clusters = (const float*)d_in[1];

    float* q_out = (float*)d_out;
    float* c_out = (float*)d_out + (size_t)N_ * K_;

    prep_kernel<<<32, 256>>>(clusters);
    gemm_kernel<<<N_ / BM, 256>>>(x, q_out);
    row_kernel<<<N_ / 64, 512>>>(q_out);
    pass2_kernel<<<N_ / 8, 256>>>(q_out, x);
    if (out_size >= (int)((size_t)N_ * K_ + (size_t)K_ * D_)) {
        finalize_kernel<<<(K_ * D_) / 256, 256>>>(c_out);
    }
}

// round 15
// speedup vs baseline: 1.0852x; 1.0229x over previous
#include <cuda_runtime.h>
#include <cuda_bf16.h>
#include <mma.h>
#include <cstdint>

using namespace nvcuda;

#define N_ 65536
#define D_ 1024
#define K_ 256

#define BM 64
#define BK 32
#define LDS_B 40   /* bf16 per smem row: 32 + 8 pad */

static __device__ __align__(16) __nv_bfloat16 g_cb[K_ * D_];
static __device__ __align__(16) float g_csq[K_];
static __device__ __align__(16) float g_xsq[N_];
static __device__ __align__(16) float g_qsum[K_];
static __device__ __align__(16) float g_num[K_ * D_];
static __device__ __align__(16) float g_den[K_];

// ---------------------------------------------------------------------------
// Kernel 1: clusters fp32 -> bf16, ||c||^2, zero accumulators.
// ---------------------------------------------------------------------------
__global__ void prep_kernel(const float* __restrict__ clusters) {
    int gtid = blockIdx.x * blockDim.x + threadIdx.x;
    int w    = gtid >> 5;
    int lane = threadIdx.x & 31;

    if (w < K_) {
        const float* src = clusters + (size_t)w * D_;
        __nv_bfloat16* dst = g_cb + (size_t)w * D_;
        float s = 0.f;
        #pragma unroll
        for (int c = lane; c < D_; c += 32) {
            float v = src[c];
            s += v * v;
            dst[c] = __float2bfloat16(v);
        }
        #pragma unroll
        for (int o = 16; o; o >>= 1) s += __shfl_xor_sync(0xffffffffu, s, o);
        if (lane == 0) g_csq[w] = s;
    }

    if (gtid < K_) { g_qsum[gtid] = 0.f; g_den[gtid] = 0.f; }
    for (int i = gtid; i < K_ * D_; i += 8192) g_num[i] = 0.f;
}

// ---------------------------------------------------------------------------
// Kernel 2: wmma bf16 GEMM, 64x256 (full K) tile, BK=32, DOUBLE-buffered
// static smem, ONE barrier per k-iteration. 256 threads = 8 warps (2m x 4n),
// warp tile 32x64, 2 CTAs/SM. Fuses ||x||^2. Writes RAW dot products.
// ---------------------------------------------------------------------------
__global__ __launch_bounds__(256, 2)
void gemm_kernel(const float* __restrict__ x, float* __restrict__ q_out) {
    __shared__ __align__(16) __nv_bfloat16 As[2][BM * LDS_B];  /* 2x 5120 B */
    __shared__ __align__(16) __nv_bfloat16 Bs[2][K_ * LDS_B];  /* 2x20480 B */
    __shared__ float xsq_s[BM];

    const int tid  = threadIdx.x;
    const int wid  = tid >> 5;       // 0..7
    const int wm   = wid & 1;        // 32-row group
    const int wn   = wid >> 1;       // 64-col group
    const int row0 = blockIdx.x * BM;

    if (tid < 64) xsq_s[tid] = 0.f;

    // loaders: A 4 thr/row x 8 floats; B 4 thr/row x 8 bf16, 4 rows/thread
    const int aRow = tid >> 2;            // 0..63
    const int aCol = (tid & 3) * 8;       // 0..24 (floats)
    const int bRow = tid >> 2;            // 0..63 (+64*i)
    const int bCol = (tid & 3) * 8;       // 0..24 (bf16)

    const float* aP = x + (size_t)(row0 + aRow) * D_ + aCol;
    const __nv_bfloat16* bP = g_cb + (size_t)bRow * D_ + bCol;

    wmma::fragment<wmma::accumulator, 16, 16, 16, float> acc[2][4];
    #pragma unroll
    for (int mi = 0; mi < 2; mi++)
        #pragma unroll
        for (int nj = 0; nj < 4; nj++)
            wmma::fill_fragment(acc[mi][nj], 0.f);

    float4 a0, a1;
    uint4  bv[4];
    float sq = 0.f;

    // --- prologue: tile 0 -> buf 0; stage tile 1 in regs ---
    a0 = *(const float4*)aP;
    a1 = *(const float4*)(aP + 4);
    #pragma unroll
    for (int i = 0; i < 4; i++)
        bv[i] = *(const uint4*)(bP + (size_t)i * 64 * D_);
    {
        __nv_bfloat162* da = (__nv_bfloat162*)&As[0][aRow * LDS_B + aCol];
        __nv_bfloat162 p;
        p.x = __float2bfloat16(a0.x); p.y = __float2bfloat16(a0.y); da[0] = p;
        p.x = __float2bfloat16(a0.z); p.y = __float2bfloat16(a0.w); da[1] = p;
        p.x = __float2bfloat16(a1.x); p.y = __float2bfloat16(a1.y); da[2] = p;
        p.x = __float2bfloat16(a1.z); p.y = __float2bfloat16(a1.w); da[3] = p;
        sq += a0.x*a0.x + a0.y*a0.y + a0.z*a0.z + a0.w*a0.w
            + a1.x*a1.x + a1.y*a1.y + a1.z*a1.z + a1.w*a1.w;
        #pragma unroll
        for (int i = 0; i < 4; i++)
            *(uint4*)&Bs[0][(bRow + i * 64) * LDS_B + bCol] = bv[i];
    }
    a0 = *(const float4*)(aP + BK);
    a1 = *(const float4*)(aP + BK + 4);
    #pragma unroll
    for (int i = 0; i < 4; i++)
        bv[i] = *(const uint4*)(bP + BK + (size_t)i * 64 * D_);
    __syncthreads();

    for (int kt = 0; kt < D_ / BK; ++kt) {
        // commit staged tile kt+1 into the other buffer (no hazard)
        if (kt < D_ / BK - 1) {
            const int nb = (kt + 1) & 1;
            __nv_bfloat162* da = (__nv_bfloat162*)&As[nb][aRow * LDS_B + aCol];
            __nv_bfloat162 p;
            p.x = __float2bfloat16(a0.x); p.y = __float2bfloat16(a0.y); da[0] = p;
            p.x = __float2bfloat16(a0.z); p.y = __float2bfloat16(a0.w); da[1] = p;
            p.x = __float2bfloat16(a1.x); p.y = __float2bfloat16(a1.y); da[2] = p;
            p.x = __float2bfloat16(a1.z); p.y = __float2bfloat16(a1.w); da[3] = p;
            sq += a0.x*a0.x + a0.y*a0.y + a0.z*a0.z + a0.w*a0.w
                + a1.x*a1.x + a1.y*a1.y + a1.z*a1.z + a1.w*a1.w;
            #pragma unroll
            for (int i = 0; i < 4; i++)
                *(uint4*)&Bs[nb][(bRow + i * 64) * LDS_B + bCol] = bv[i];
        }

        // prefetch tile kt+2 into regs (overlaps mma)
        if (kt < D_ / BK - 2) {
            const float* ap = aP + (kt + 2) * BK;
            const __nv_bfloat16* bp = bP + (kt + 2) * BK;
            a0 = *(const float4*)ap;
            a1 = *(const float4*)(ap + 4);
            #pragma unroll
            for (int i = 0; i < 4; i++)
                bv[i] = *(const uint4*)(bp + (size_t)i * 64 * D_);
        }

        // mma on buffer kt&1: 2 k16 steps, 32x64 warp tile
        const int cb = kt & 1;
        #pragma unroll
        for (int ks = 0; ks < 2; ++ks) {
            wmma::fragment<wmma::matrix_b, 16, 16, 16, __nv_bfloat16,
                           wmma::col_major> bfr[4];
            #pragma unroll
            for (int nj = 0; nj < 4; nj++)
                wmma::load_matrix_sync(
                    bfr[nj], &Bs[cb][(wn * 64 + nj * 16) * LDS_B + ks * 16], LDS_B);
            #pragma unroll
            for (int mi = 0; mi < 2; mi++) {
                wmma::fragment<wmma::matrix_a, 16, 16, 16, __nv_bfloat16,
                               wmma::row_major> afr;
                wmma::load_matrix_sync(
                    afr, &As[cb][(wm * 32 + mi * 16) * LDS_B + ks * 16], LDS_B);
                #pragma unroll
                for (int nj = 0; nj < 4; nj++)
                    wmma::mma_sync(acc[mi][nj], afr, bfr[nj], acc[mi][nj]);
            }
        }
        __syncthreads();
    }

    // ||x||^2 publish (4 partials per row)
    atomicAdd(&xsq_s[aRow], sq);
    __syncthreads();
    if (tid < 64) g_xsq[row0 + tid] = xsq_s[tid];

    // store raw dot products
    #pragma unroll
    for (int mi = 0; mi < 2; mi++)
        #pragma unroll
        for (int nj = 0; nj < 4; nj++)
            wmma::store_matrix_sync(
                q_out + (size_t)(row0 + wm * 32 + mi * 16) * K_
                      + wn * 64 + nj * 16,
                acc[mi][nj], K_, wmma::mem_row_major);
}

// ---------------------------------------------------------------------------
// Kernel 3: s -> t = 1/(1+d) -> row normalize in place + column sums.
// ---------------------------------------------------------------------------
__global__ __launch_bounds__(512, 2)
void row_kernel(float* __restrict__ q) {
    __shared__ float colsum[K_];
    __shared__ float csq_s[K_];
    const int tid  = threadIdx.x;
    const int lane = tid & 31;
    const int w    = tid >> 5;

    if (tid < 256) { colsum[tid] = 0.f; csq_s[tid] = g_csq[tid]; }
    __syncthreads();

    const int rbase = blockIdx.x * 64 + w * 4;
    float cacc[8] = {0.f, 0.f, 0.f, 0.f, 0.f, 0.f, 0.f, 0.f};

    const float4 c0 = *(const float4*)&csq_s[lane * 4];
    const float4 c1 = *(const float4*)&csq_s[128 + lane * 4];

    #pragma unroll
    for (int i = 0; i < 4; i++) {
        float* qr = q + (size_t)(rbase + i) * K_;
        float xs1 = 1.f + g_xsq[rbase + i];
        float4 u = *(float4*)(qr + lane * 4);
        float4 v = *(float4*)(qr + 128 + lane * 4);
        u.x = 1.f / (xs1 + c0.x - 2.f * u.x);
        u.y = 1.f / (xs1 + c0.y - 2.f * u.y);
        u.z = 1.f / (xs1 + c0.z - 2.f * u.z);
        u.w = 1.f / (xs1 + c0.w - 2.f * u.w);
        v.x = 1.f / (xs1 + c1.x - 2.f * v.x);
        v.y = 1.f / (xs1 + c1.y - 2.f * v.y);
        v.z = 1.f / (xs1 + c1.z - 2.f * v.z);
        v.w = 1.f / (xs1 + c1.w - 2.f * v.w);
        float s = u.x + u.y + u.z + u.w + v.x + v.y + v.z + v.w;
        #pragma unroll
        for (int o = 16; o; o >>= 1) s += __shfl_xor_sync(0xffffffffu, s, o);
        float inv = 1.f / s;
        u.x *= inv; u.y *= inv; u.z *= inv; u.w *= inv;
        v.x *= inv; v.y *= inv; v.z *= inv; v.w *= inv;
        *(float4*)(qr + lane * 4) = u;
        *(float4*)(qr + 128 + lane * 4) = v;
        cacc[0] += u.x; cacc[1] += u.y; cacc[2] += u.z; cacc[3] += u.w;
        cacc[4] += v.x; cacc[5] += v.y; cacc[6] += v.z; cacc[7] += v.w;
    }

    #pragma unroll
    for (int j = 0; j < 4; j++) {
        atomicAdd(&colsum[lane * 4 + j],       cacc[j]);
        atomicAdd(&colsum[128 + lane * 4 + j], cacc[4 + j]);
    }
    __syncthreads();
    if (tid < 256) atomicAdd(&g_qsum[tid], colsum[tid]);
}

// ---------------------------------------------------------------------------
// Kernel 4: sharpening + hard-assign + threshold + scatter. Warp per row.
// ---------------------------------------------------------------------------
__global__ void pass2_kernel(const float* __restrict__ q, const float* __restrict__ x) {
    int row  = blockIdx.x * (blockDim.x >> 5) + (threadIdx.x >> 5);
    int lane = threadIdx.x & 31;
    if (row >= N_) return;

    const float* qr = q + (size_t)row * K_;
    float s2 = 0.f;
    float m = -1.f;
    int   mi = 0;

    #pragma unroll
    for (int j = 0; j < 2; j++) {
        int c = (j * 32 + lane) * 4;
        float4 qv = *(const float4*)(qr + c);
        float4 qs = *(const float4*)(g_qsum + c);
        float t0 = qv.x * qv.x / qs.x;
        float t1 = qv.y * qv.y / qs.y;
        float t2 = qv.z * qv.z / qs.z;
        float t3 = qv.w * qv.w / qs.w;
        s2 += t0 + t1 + t2 + t3;
        if (t0 > m) { m = t0; mi = c; }
        if (t1 > m) { m = t1; mi = c + 1; }
        if (t2 > m) { m = t2; mi = c + 2; }
        if (t3 > m) { m = t3; mi = c + 3; }
    }
    #pragma unroll
    for (int o = 16; o; o >>= 1) {
        s2 += __shfl_xor_sync(0xffffffffu, s2, o);
        float om = __shfl_xor_sync(0xffffffffu, m, o);
        int   oi = __shfl_xor_sync(0xffffffffu, mi, o);
        if (om > m || (om == m && oi < mi)) { m = om; mi = oi; }
    }

    float val = m / s2;
    if (val > 0.1f) {
        if (lane == 0) atomicAdd(&g_den[mi], val);
        const float* xr = x + (size_t)row * D_;
        for (int c = lane; c < D_; c += 32)
            atomicAdd(&g_num[(size_t)mi * D_ + c], val * xr[c]);
    }
}

// ---------------------------------------------------------------------------
// Kernel 5: new_clusters = num / (den + eps)
// ---------------------------------------------------------------------------
__global__ void finalize_kernel(float* __restrict__ out_clusters) {
    int i = blockIdx.x * blockDim.x + threadIdx.x;
    if (i < K_ * D_) {
        int k = i / D_;
        out_clusters[i] = g_num[i] / (g_den[k] + 2.220446049250313e-16f);
    }
}

// ---------------------------------------------------------------------------
extern "C" void kernel_launch(void* const* d_in, const int* in_sizes, int n_in,
                              void* d_out, int out_size) {
    const float* x = nullptr;
    const float* clusters = nullptr;
    for (int i = 0; i < n_in; i++) {
        if (in_sizes[i] == N_ * D_)      x        = (const float*)d_in[i];
        else if (in_sizes[i] == K_ * D_) clusters = (const float*)d_in[i];
    }
    if (!x)        x        = (const float*)d_in[0];
    if (!clusters) clusters = (const float*)d_in[1];

    float* q_out = (float*)d_out;
    float* c_out = (float*)d_out + (size_t)N_ * K_;

    prep_kernel<<<32, 256>>>(clusters);
    gemm_kernel<<<N_ / BM, 256>>>(x, q_out);
    row_kernel<<<N_ / 64, 512>>>(q_out);
    pass2_kernel<<<N_ / 8, 256>>>(q_out, x);
    if (out_size >= (int)((size_t)N_ * K_ + (size_t)K_ * D_)) {
        finalize_kernel<<<(K_ * D_) / 256, 256>>>(c_out);
    }
}

// round 16
// speedup vs baseline: 1.2259x; 1.1297x over previous
#include <cuda_runtime.h>
#include <cuda_bf16.h>
#include <mma.h>
#include <cstdint>

using namespace nvcuda;

#define N_ 65536
#define D_ 1024
#define K_ 256

#define BM 64
#define BK 32
#define LDS_B 40   /* bf16 per smem row: 32 + 8 pad */

static __device__ __align__(16) __nv_bfloat16 g_cb[K_ * D_];
static __device__ __align__(16) float g_csq[K_];
static __device__ __align__(16) float g_qsum[K_];
static __device__ __align__(16) float g_num[K_ * D_];
static __device__ __align__(16) float g_den[K_];

// ---------------------------------------------------------------------------
// Kernel 1: clusters fp32 -> bf16, ||c||^2, zero accumulators.
// ---------------------------------------------------------------------------
__global__ void prep_kernel(const float* __restrict__ clusters) {
    int gtid = blockIdx.x * blockDim.x + threadIdx.x;
    int w    = gtid >> 5;
    int lane = threadIdx.x & 31;

    if (w < K_) {
        const float* src = clusters + (size_t)w * D_;
        __nv_bfloat16* dst = g_cb + (size_t)w * D_;
        float s = 0.f;
        #pragma unroll
        for (int c = lane; c < D_; c += 32) {
            float v = src[c];
            s += v * v;
            dst[c] = __float2bfloat16(v);
        }
        #pragma unroll
        for (int o = 16; o; o >>= 1) s += __shfl_xor_sync(0xffffffffu, s, o);
        if (lane == 0) g_csq[w] = s;
    }

    if (gtid < K_) { g_qsum[gtid] = 0.f; g_den[gtid] = 0.f; }
    for (int i = gtid; i < K_ * D_; i += 8192) g_num[i] = 0.f;
}

// ---------------------------------------------------------------------------
// Kernel 2: wmma bf16 GEMM (R15 mainloop, untouched: 64x256 full-K, BK=32,
// double-buffered static smem, one barrier/iter, 8 warps 32x64, 2 CTAs/SM)
// + FUSED epilogue via L2 roundtrip (overlaps the co-resident CTA's
// mainloop): raw dots -> q_out, sync, read back, t=1/(1+d), row-normalize,
// overwrite final q, column sums -> g_qsum. Fuses ||x||^2.
// ---------------------------------------------------------------------------
__global__ __launch_bounds__(256, 2)
void gemm_kernel(const float* __restrict__ x, float* __restrict__ q_out) {
    __shared__ __align__(16) __nv_bfloat16 As[2][BM * LDS_B];  /* 2x 5120 B */
    __shared__ __align__(16) __nv_bfloat16 Bs[2][K_ * LDS_B];  /* 2x20480 B */
    __shared__ float xsq_s[BM];
    __shared__ float csq_s[K_];
    __shared__ float colsum[K_];

    const int tid  = threadIdx.x;
    const int lane = tid & 31;
    const int wid  = tid >> 5;       // 0..7
    const int wm   = wid & 1;        // 32-row group
    const int wn   = wid >> 1;       // 64-col group
    const int row0 = blockIdx.x * BM;

    if (tid < 64) xsq_s[tid] = 0.f;
    if (tid < 256) { csq_s[tid] = g_csq[tid]; colsum[tid] = 0.f; }

    // loaders: A 4 thr/row x 8 floats; B 4 thr/row x 8 bf16, 4 rows/thread
    const int aRow = tid >> 2;            // 0..63
    const int aCol = (tid & 3) * 8;       // 0..24 (floats)
    const int bRow = tid >> 2;            // 0..63 (+64*i)
    const int bCol = (tid & 3) * 8;       // 0..24 (bf16)

    const float* aP = x + (size_t)(row0 + aRow) * D_ + aCol;
    const __nv_bfloat16* bP = g_cb + (size_t)bRow * D_ + bCol;

    wmma::fragment<wmma::accumulator, 16, 16, 16, float> acc[2][4];
    #pragma unroll
    for (int mi = 0; mi < 2; mi++)
        #pragma unroll
        for (int nj = 0; nj < 4; nj++)
            wmma::fill_fragment(acc[mi][nj], 0.f);

    float4 a0, a1;
    uint4  bv[4];
    float sq = 0.f;

    // --- prologue: tile 0 -> buf 0; stage tile 1 in regs ---
    a0 = *(const float4*)aP;
    a1 = *(const float4*)(aP + 4);
    #pragma unroll
    for (int i = 0; i < 4; i++)
        bv[i] = *(const uint4*)(bP + (size_t)i * 64 * D_);
    {
        __nv_bfloat162* da = (__nv_bfloat162*)&As[0][aRow * LDS_B + aCol];
        __nv_bfloat162 p;
        p.x = __float2bfloat16(a0.x); p.y = __float2bfloat16(a0.y); da[0] = p;
        p.x = __float2bfloat16(a0.z); p.y = __float2bfloat16(a0.w); da[1] = p;
        p.x = __float2bfloat16(a1.x); p.y = __float2bfloat16(a1.y); da[2] = p;
        p.x = __float2bfloat16(a1.z); p.y = __float2bfloat16(a1.w); da[3] = p;
        sq += a0.x*a0.x + a0.y*a0.y + a0.z*a0.z + a0.w*a0.w
            + a1.x*a1.x + a1.y*a1.y + a1.z*a1.z + a1.w*a1.w;
        #pragma unroll
        for (int i = 0; i < 4; i++)
            *(uint4*)&Bs[0][(bRow + i * 64) * LDS_B + bCol] = bv[i];
    }
    a0 = *(const float4*)(aP + BK);
    a1 = *(const float4*)(aP + BK + 4);
    #pragma unroll
    for (int i = 0; i < 4; i++)
        bv[i] = *(const uint4*)(bP + BK + (size_t)i * 64 * D_);
    __syncthreads();

    for (int kt = 0; kt < D_ / BK; ++kt) {
        // commit staged tile kt+1 into the other buffer (no hazard)
        if (kt < D_ / BK - 1) {
            const int nb = (kt + 1) & 1;
            __nv_bfloat162* da = (__nv_bfloat162*)&As[nb][aRow * LDS_B + aCol];
            __nv_bfloat162 p;
            p.x = __float2bfloat16(a0.x); p.y = __float2bfloat16(a0.y); da[0] = p;
            p.x = __float2bfloat16(a0.z); p.y = __float2bfloat16(a0.w); da[1] = p;
            p.x = __float2bfloat16(a1.x); p.y = __float2bfloat16(a1.y); da[2] = p;
            p.x = __float2bfloat16(a1.z); p.y = __float2bfloat16(a1.w); da[3] = p;
            sq += a0.x*a0.x + a0.y*a0.y + a0.z*a0.z + a0.w*a0.w
                + a1.x*a1.x + a1.y*a1.y + a1.z*a1.z + a1.w*a1.w;
            #pragma unroll
            for (int i = 0; i < 4; i++)
                *(uint4*)&Bs[nb][(bRow + i * 64) * LDS_B + bCol] = bv[i];
        }

        // prefetch tile kt+2 into regs (overlaps mma)
        if (kt < D_ / BK - 2) {
            const float* ap = aP + (kt + 2) * BK;
            const __nv_bfloat16* bp = bP + (kt + 2) * BK;
            a0 = *(const float4*)ap;
            a1 = *(const float4*)(ap + 4);
            #pragma unroll
            for (int i = 0; i < 4; i++)
                bv[i] = *(const uint4*)(bp + (size_t)i * 64 * D_);
        }

        // mma on buffer kt&1: 2 k16 steps, 32x64 warp tile
        const int cb = kt & 1;
        #pragma unroll
        for (int ks = 0; ks < 2; ++ks) {
            wmma::fragment<wmma::matrix_b, 16, 16, 16, __nv_bfloat16,
                           wmma::col_major> bfr[4];
            #pragma unroll
            for (int nj = 0; nj < 4; nj++)
                wmma::load_matrix_sync(
                    bfr[nj], &Bs[cb][(wn * 64 + nj * 16) * LDS_B + ks * 16], LDS_B);
            #pragma unroll
            for (int mi = 0; mi < 2; mi++) {
                wmma::fragment<wmma::matrix_a, 16, 16, 16, __nv_bfloat16,
                               wmma::row_major> afr;
                wmma::load_matrix_sync(
                    afr, &As[cb][(wm * 32 + mi * 16) * LDS_B + ks * 16], LDS_B);
                #pragma unroll
                for (int nj = 0; nj < 4; nj++)
                    wmma::mma_sync(acc[mi][nj], afr, bfr[nj], acc[mi][nj]);
            }
        }
        __syncthreads();
    }

    // ||x||^2 publish (4 partials per row)
    atomicAdd(&xsq_s[aRow], sq);

    // dump raw dot products to q_out (stays hot in L2)
    #pragma unroll
    for (int mi = 0; mi < 2; mi++)
        #pragma unroll
        for (int nj = 0; nj < 4; nj++)
            wmma::store_matrix_sync(
                q_out + (size_t)(row0 + wm * 32 + mi * 16) * K_
                      + wn * 64 + nj * 16,
                acc[mi][nj], K_, wmma::mem_row_major);
    __syncthreads();   // orders global stores + xsq within the CTA

    // fused epilogue (reads back via L2): each warp handles 8 rows
    {
        const float4 c0 = *(const float4*)&csq_s[lane * 4];
        const float4 c1 = *(const float4*)&csq_s[128 + lane * 4];
        float cacc[8] = {0.f, 0.f, 0.f, 0.f, 0.f, 0.f, 0.f, 0.f};

        #pragma unroll
        for (int i = 0; i < 8; i++) {
            const int row = wid * 8 + i;
            float* go = q_out + (size_t)(row0 + row) * K_;
            float xs1 = 1.f + xsq_s[row];
            float4 u = *(float4*)(go + lane * 4);
            float4 v = *(float4*)(go + 128 + lane * 4);
            u.x = 1.f / (xs1 + c0.x - 2.f * u.x);
            u.y = 1.f / (xs1 + c0.y - 2.f * u.y);
            u.z = 1.f / (xs1 + c0.z - 2.f * u.z);
            u.w = 1.f / (xs1 + c0.w - 2.f * u.w);
            v.x = 1.f / (xs1 + c1.x - 2.f * v.x);
            v.y = 1.f / (xs1 + c1.y - 2.f * v.y);
            v.z = 1.f / (xs1 + c1.z - 2.f * v.z);
            v.w = 1.f / (xs1 + c1.w - 2.f * v.w);
            float s = u.x + u.y + u.z + u.w + v.x + v.y + v.z + v.w;
            #pragma unroll
            for (int o = 16; o; o >>= 1) s += __shfl_xor_sync(0xffffffffu, s, o);
            float inv = 1.f / s;
            u.x *= inv; u.y *= inv; u.z *= inv; u.w *= inv;
            v.x *= inv; v.y *= inv; v.z *= inv; v.w *= inv;
            *(float4*)(go + lane * 4) = u;
            *(float4*)(go + 128 + lane * 4) = v;
            cacc[0] += u.x; cacc[1] += u.y; cacc[2] += u.z; cacc[3] += u.w;
            cacc[4] += v.x; cacc[5] += v.y; cacc[6] += v.z; cacc[7] += v.w;
        }

        #pragma unroll
        for (int j = 0; j < 4; j++) {
            atomicAdd(&colsum[lane * 4 + j],       cacc[j]);
            atomicAdd(&colsum[128 + lane * 4 + j], cacc[4 + j]);
        }
    }
    __syncthreads();
    if (tid < 256) atomicAdd(&g_qsum[tid], colsum[tid]);
}

// ---------------------------------------------------------------------------
// Kernel 3: sharpening + hard-assign + threshold + scatter. Warp per row.
// ---------------------------------------------------------------------------
__global__ void pass2_kernel(const float* __restrict__ q, const float* __restrict__ x) {
    int row  = blockIdx.x * (blockDim.x >> 5) + (threadIdx.x >> 5);
    int lane = threadIdx.x & 31;
    if (row >= N_) return;

    const float* qr = q + (size_t)row * K_;
    float s2 = 0.f;
    float m = -1.f;
    int   mi = 0;

    #pragma unroll
    for (int j = 0; j < 2; j++) {
        int c = (j * 32 + lane) * 4;
        float4 qv = *(const float4*)(qr + c);
        float4 qs = *(const float4*)(g_qsum + c);
        float t0 = qv.x * qv.x / qs.x;
        float t1 = qv.y * qv.y / qs.y;
        float t2 = qv.z * qv.z / qs.z;
        float t3 = qv.w * qv.w / qs.w;
        s2 += t0 + t1 + t2 + t3;
        if (t0 > m) { m = t0; mi = c; }
        if (t1 > m) { m = t1; mi = c + 1; }
        if (t2 > m) { m = t2; mi = c + 2; }
        if (t3 > m) { m = t3; mi = c + 3; }
    }
    #pragma unroll
    for (int o = 16; o; o >>= 1) {
        s2 += __shfl_xor_sync(0xffffffffu, s2, o);
        float om = __shfl_xor_sync(0xffffffffu, m, o);
        int   oi = __shfl_xor_sync(0xffffffffu, mi, o);
        if (om > m || (om == m && oi < mi)) { m = om; mi = oi; }
    }

    float val = m / s2;
    if (val > 0.1f) {
        if (lane == 0) atomicAdd(&g_den[mi], val);
        const float* xr = x + (size_t)row * D_;
        for (int c = lane; c < D_; c += 32)
            atomicAdd(&g_num[(size_t)mi * D_ + c], val * xr[c]);
    }
}

// ---------------------------------------------------------------------------
// Kernel 4: new_clusters = num / (den + eps)
// ---------------------------------------------------------------------------
__global__ void finalize_kernel(float* __restrict__ out_clusters) {
    int i = blockIdx.x * blockDim.x + threadIdx.x;
    if (i < K_ * D_) {
        int k = i / D_;
        out_clusters[i] = g_num[i] / (g_den[k] + 2.220446049250313e-16f);
    }
}

// ---------------------------------------------------------------------------
extern "C" void kernel_launch(void* const* d_in, const int* in_sizes, int n_in,
                              void* d_out, int out_size) {
    const float* x = nullptr;
    const float* clusters = nullptr;
    for (int i = 0; i < n_in; i++) {
        if (in_sizes[i] == N_ * D_)      x        = (const float*)d_in[i];
        else if (in_sizes[i] == K_ * D_) clusters = (const float*)d_in[i];
    }
    if (!x)        x        = (const float*)d_in[0];
    if (!clusters) clusters = (const float*)d_in[1];

    float* q_out = (float*)d_out;
    float* c_out = (float*)d_out + (size_t)N_ * K_;

    prep_kernel<<<32, 256>>>(clusters);
    gemm_kernel<<<N_ / BM, 256>>>(x, q_out);
    pass2_kernel<<<N_ / 8, 256>>>(q_out, x);
    if (out_size >= (int)((size_t)N_ * K_ + (size_t)K_ * D_)) {
        finalize_kernel<<<(K_ * D_) / 256, 256>>>(c_out);
    }
}

// round 17
// speedup vs baseline: 1.2506x; 1.0202x over previous
#include <cuda_runtime.h>
#include <cuda_bf16.h>
#include <mma.h>
#include <cstdint>

using namespace nvcuda;

#define N_ 65536
#define D_ 1024
#define K_ 256

#define BM 64
#define BK 32
#define LDS_B 40   /* bf16 per smem row: 32 + 8 pad */

static __device__ __align__(16) __nv_bfloat16 g_cb[K_ * D_];
static __device__ __align__(16) float g_csq[K_];
static __device__ __align__(16) float g_qsum[K_];
static __device__ __align__(16) float g_num[K_ * D_];
static __device__ __align__(16) float g_den[K_];

// ---------------------------------------------------------------------------
// Kernel 1: clusters fp32 -> bf16, ||c||^2, zero accumulators. 128 blocks.
// ---------------------------------------------------------------------------
__global__ void prep_kernel(const float* __restrict__ clusters) {
    int gtid = blockIdx.x * blockDim.x + threadIdx.x;   // 0..32767
    int w    = gtid >> 5;                               // 0..1023
    int lane = threadIdx.x & 31;

    if (w < K_) {
        const float* src = clusters + (size_t)w * D_;
        __nv_bfloat16* dst = g_cb + (size_t)w * D_;
        float s = 0.f;
        #pragma unroll
        for (int c = lane; c < D_; c += 32) {
            float v = src[c];
            s += v * v;
            dst[c] = __float2bfloat16(v);
        }
        #pragma unroll
        for (int o = 16; o; o >>= 1) s += __shfl_xor_sync(0xffffffffu, s, o);
        if (lane == 0) g_csq[w] = s;
    }

    if (gtid < K_) { g_qsum[gtid] = 0.f; g_den[gtid] = 0.f; }
    for (int i = gtid; i < K_ * D_; i += 32768) g_num[i] = 0.f;
}

// ---------------------------------------------------------------------------
// Kernel 2: wmma bf16 GEMM (R15 mainloop, untouched) + fused epilogue via L2
// roundtrip (overlaps co-resident CTA's mainloop). Unchanged from R16.
// ---------------------------------------------------------------------------
__global__ __launch_bounds__(256, 2)
void gemm_kernel(const float* __restrict__ x, float* __restrict__ q_out) {
    __shared__ __align__(16) __nv_bfloat16 As[2][BM * LDS_B];  /* 2x 5120 B */
    __shared__ __align__(16) __nv_bfloat16 Bs[2][K_ * LDS_B];  /* 2x20480 B */
    __shared__ float xsq_s[BM];
    __shared__ float csq_s[K_];
    __shared__ float colsum[K_];

    const int tid  = threadIdx.x;
    const int lane = tid & 31;
    const int wid  = tid >> 5;       // 0..7
    const int wm   = wid & 1;        // 32-row group
    const int wn   = wid >> 1;       // 64-col group
    const int row0 = blockIdx.x * BM;

    if (tid < 64) xsq_s[tid] = 0.f;
    if (tid < 256) { csq_s[tid] = g_csq[tid]; colsum[tid] = 0.f; }

    const int aRow = tid >> 2;            // 0..63
    const int aCol = (tid & 3) * 8;       // 0..24 (floats)
    const int bRow = tid >> 2;            // 0..63 (+64*i)
    const int bCol = (tid & 3) * 8;       // 0..24 (bf16)

    const float* aP = x + (size_t)(row0 + aRow) * D_ + aCol;
    const __nv_bfloat16* bP = g_cb + (size_t)bRow * D_ + bCol;

    wmma::fragment<wmma::accumulator, 16, 16, 16, float> acc[2][4];
    #pragma unroll
    for (int mi = 0; mi < 2; mi++)
        #pragma unroll
        for (int nj = 0; nj < 4; nj++)
            wmma::fill_fragment(acc[mi][nj], 0.f);

    float4 a0, a1;
    uint4  bv[4];
    float sq = 0.f;

    // prologue: tile 0 -> buf 0; stage tile 1 in regs
    a0 = *(const float4*)aP;
    a1 = *(const float4*)(aP + 4);
    #pragma unroll
    for (int i = 0; i < 4; i++)
        bv[i] = *(const uint4*)(bP + (size_t)i * 64 * D_);
    {
        __nv_bfloat162* da = (__nv_bfloat162*)&As[0][aRow * LDS_B + aCol];
        __nv_bfloat162 p;
        p.x = __float2bfloat16(a0.x); p.y = __float2bfloat16(a0.y); da[0] = p;
        p.x = __float2bfloat16(a0.z); p.y = __float2bfloat16(a0.w); da[1] = p;
        p.x = __float2bfloat16(a1.x); p.y = __float2bfloat16(a1.y); da[2] = p;
        p.x = __float2bfloat16(a1.z); p.y = __float2bfloat16(a1.w); da[3] = p;
        sq += a0.x*a0.x + a0.y*a0.y + a0.z*a0.z + a0.w*a0.w
            + a1.x*a1.x + a1.y*a1.y + a1.z*a1.z + a1.w*a1.w;
        #pragma unroll
        for (int i = 0; i < 4; i++)
            *(uint4*)&Bs[0][(bRow + i * 64) * LDS_B + bCol] = bv[i];
    }
    a0 = *(const float4*)(aP + BK);
    a1 = *(const float4*)(aP + BK + 4);
    #pragma unroll
    for (int i = 0; i < 4; i++)
        bv[i] = *(const uint4*)(bP + BK + (size_t)i * 64 * D_);
    __syncthreads();

    for (int kt = 0; kt < D_ / BK; ++kt) {
        if (kt < D_ / BK - 1) {
            const int nb = (kt + 1) & 1;
            __nv_bfloat162* da = (__nv_bfloat162*)&As[nb][aRow * LDS_B + aCol];
            __nv_bfloat162 p;
            p.x = __float2bfloat16(a0.x); p.y = __float2bfloat16(a0.y); da[0] = p;
            p.x = __float2bfloat16(a0.z); p.y = __float2bfloat16(a0.w); da[1] = p;
            p.x = __float2bfloat16(a1.x); p.y = __float2bfloat16(a1.y); da[2] = p;
            p.x = __float2bfloat16(a1.z); p.y = __float2bfloat16(a1.w); da[3] = p;
            sq += a0.x*a0.x + a0.y*a0.y + a0.z*a0.z + a0.w*a0.w
                + a1.x*a1.x + a1.y*a1.y + a1.z*a1.z + a1.w*a1.w;
            #pragma unroll
            for (int i = 0; i < 4; i++)
                *(uint4*)&Bs[nb][(bRow + i * 64) * LDS_B + bCol] = bv[i];
        }

        if (kt < D_ / BK - 2) {
            const float* ap = aP + (kt + 2) * BK;
            const __nv_bfloat16* bp = bP + (kt + 2) * BK;
            a0 = *(const float4*)ap;
            a1 = *(const float4*)(ap + 4);
            #pragma unroll
            for (int i = 0; i < 4; i++)
                bv[i] = *(const uint4*)(bp + (size_t)i * 64 * D_);
        }

        const int cb = kt & 1;
        #pragma unroll
        for (int ks = 0; ks < 2; ++ks) {
            wmma::fragment<wmma::matrix_b, 16, 16, 16, __nv_bfloat16,
                           wmma::col_major> bfr[4];
            #pragma unroll
            for (int nj = 0; nj < 4; nj++)
                wmma::load_matrix_sync(
                    bfr[nj], &Bs[cb][(wn * 64 + nj * 16) * LDS_B + ks * 16], LDS_B);
            #pragma unroll
            for (int mi = 0; mi < 2; mi++) {
                wmma::fragment<wmma::matrix_a, 16, 16, 16, __nv_bfloat16,
                               wmma::row_major> afr;
                wmma::load_matrix_sync(
                    afr, &As[cb][(wm * 32 + mi * 16) * LDS_B + ks * 16], LDS_B);
                #pragma unroll
                for (int nj = 0; nj < 4; nj++)
                    wmma::mma_sync(acc[mi][nj], afr, bfr[nj], acc[mi][nj]);
            }
        }
        __syncthreads();
    }

    atomicAdd(&xsq_s[aRow], sq);

    #pragma unroll
    for (int mi = 0; mi < 2; mi++)
        #pragma unroll
        for (int nj = 0; nj < 4; nj++)
            wmma::store_matrix_sync(
                q_out + (size_t)(row0 + wm * 32 + mi * 16) * K_
                      + wn * 64 + nj * 16,
                acc[mi][nj], K_, wmma::mem_row_major);
    __syncthreads();

    // fused epilogue (reads back via L2): each warp handles 8 rows
    {
        const float4 c0 = *(const float4*)&csq_s[lane * 4];
        const float4 c1 = *(const float4*)&csq_s[128 + lane * 4];
        float cacc[8] = {0.f, 0.f, 0.f, 0.f, 0.f, 0.f, 0.f, 0.f};

        #pragma unroll
        for (int i = 0; i < 8; i++) {
            const int row = wid * 8 + i;
            float* go = q_out + (size_t)(row0 + row) * K_;
            float xs1 = 1.f + xsq_s[row];
            float4 u = *(float4*)(go + lane * 4);
            float4 v = *(float4*)(go + 128 + lane * 4);
            u.x = 1.f / (xs1 + c0.x - 2.f * u.x);
            u.y = 1.f / (xs1 + c0.y - 2.f * u.y);
            u.z = 1.f / (xs1 + c0.z - 2.f * u.z);
            u.w = 1.f / (xs1 + c0.w - 2.f * u.w);
            v.x = 1.f / (xs1 + c1.x - 2.f * v.x);
            v.y = 1.f / (xs1 + c1.y - 2.f * v.y);
            v.z = 1.f / (xs1 + c1.z - 2.f * v.z);
            v.w = 1.f / (xs1 + c1.w - 2.f * v.w);
            float s = u.x + u.y + u.z + u.w + v.x + v.y + v.z + v.w;
            #pragma unroll
            for (int o = 16; o; o >>= 1) s += __shfl_xor_sync(0xffffffffu, s, o);
            float inv = 1.f / s;
            u.x *= inv; u.y *= inv; u.z *= inv; u.w *= inv;
            v.x *= inv; v.y *= inv; v.z *= inv; v.w *= inv;
            *(float4*)(go + lane * 4) = u;
            *(float4*)(go + 128 + lane * 4) = v;
            cacc[0] += u.x; cacc[1] += u.y; cacc[2] += u.z; cacc[3] += u.w;
            cacc[4] += v.x; cacc[5] += v.y; cacc[6] += v.z; cacc[7] += v.w;
        }

        #pragma unroll
        for (int j = 0; j < 4; j++) {
            atomicAdd(&colsum[lane * 4 + j],       cacc[j]);
            atomicAdd(&colsum[128 + lane * 4 + j], cacc[4 + j]);
        }
    }
    __syncthreads();
    if (tid < 256) atomicAdd(&g_qsum[tid], colsum[tid]);
}

// ---------------------------------------------------------------------------
// Kernel 3: sharpening + hard-assign + threshold + scatter. Warp per row.
// Per-block smem 1/q_sum (256 divides/block instead of 2048).
// ---------------------------------------------------------------------------
__global__ __launch_bounds__(256, 4)
void pass2_kernel(const float* __restrict__ q, const float* __restrict__ x) {
    __shared__ float qinv[K_];
    if (threadIdx.x < 256) qinv[threadIdx.x] = 1.0f / g_qsum[threadIdx.x];
    __syncthreads();

    int row  = blockIdx.x * (blockDim.x >> 5) + (threadIdx.x >> 5);
    int lane = threadIdx.x & 31;
    if (row >= N_) return;

    const float* qr = q + (size_t)row * K_;
    float s2 = 0.f;
    float m = -1.f;
    int   mi = 0;

    #pragma unroll
    for (int j = 0; j < 2; j++) {
        int c = (j * 32 + lane) * 4;
        float4 qv = *(const float4*)(qr + c);
        float4 qi = *(const float4*)(qinv + c);
        float t0 = qv.x * qv.x * qi.x;
        float t1 = qv.y * qv.y * qi.y;
        float t2 = qv.z * qv.z * qi.z;
        float t3 = qv.w * qv.w * qi.w;
        s2 += t0 + t1 + t2 + t3;
        if (t0 > m) { m = t0; mi = c; }
        if (t1 > m) { m = t1; mi = c + 1; }
        if (t2 > m) { m = t2; mi = c + 2; }
        if (t3 > m) { m = t3; mi = c + 3; }
    }
    #pragma unroll
    for (int o = 16; o; o >>= 1) {
        s2 += __shfl_xor_sync(0xffffffffu, s2, o);
        float om = __shfl_xor_sync(0xffffffffu, m, o);
        int   oi = __shfl_xor_sync(0xffffffffu, mi, o);
        if (om > m || (om == m && oi < mi)) { m = om; mi = oi; }
    }

    float val = m / s2;
    if (val > 0.1f) {
        if (lane == 0) atomicAdd(&g_den[mi], val);
        const float* xr = x + (size_t)row * D_;
        for (int c = lane; c < D_; c += 32)
            atomicAdd(&g_num[(size_t)mi * D_ + c], val * xr[c]);
    }
}

// ---------------------------------------------------------------------------
// Kernel 4: new_clusters = num / (den + eps), float4-vectorized.
// ---------------------------------------------------------------------------
__global__ void finalize_kernel(float* __restrict__ out_clusters) {
    int i = blockIdx.x * blockDim.x + threadIdx.x;   // float4 index
    if (i < K_ * D_ / 4) {
        int k = i / (D_ / 4);
        float inv = 1.0f / (g_den[k] + 2.220446049250313e-16f);
        float4 v = *(const float4*)(g_num + i * 4);
        v.x *= inv; v.y *= inv; v.z *= inv; v.w *= inv;
        *(float4*)(out_clusters + i * 4) = v;
    }
}

// ---------------------------------------------------------------------------
extern "C" void kernel_launch(void* const* d_in, const int* in_sizes, int n_in,
                              void* d_out, int out_size) {
    const float* x = nullptr;
    const float* clusters = nullptr;
    for (int i = 0; i < n_in; i++) {
        if (in_sizes[i] == N_ * D_)      x        = (const float*)d_in[i];
        else if (in_sizes[i] == K_ * D_) clusters = (const float*)d_in[i];
    }
    if (!x)        x        = (const float*)d_in[0];
    if (!clusters) clusters = (const float*)d_in[1];

    float* q_out = (float*)d_out;
    float* c_out = (float*)d_out + (size_t)N_ * K_;

    prep_kernel<<<128, 256>>>(clusters);
    gemm_kernel<<<N_ / BM, 256>>>(x, q_out);
    pass2_kernel<<<N_ / 8, 256>>>(q_out, x);
    if (out_size >= (int)((size_t)N_ * K_ + (size_t)K_ * D_)) {
        finalize_kernel<<<(K_ * D_ / 4 + 255) / 256, 256>>>(c_out);
    }
}